// round 17
// baseline (speedup 1.0000x reference)
#include <cuda_runtime.h>
#include <cuda_bf16.h>
#include <cuda_fp16.h>
#include <cstdint>

#define BB 2
#define SS 2048
#define EE 512
#define HH 8
#define DD 64
#define NKV ((size_t)BB * SS * HH * DD)   // 2097152
#define NAC ((size_t)BB * SS * EE)        // 2097152

typedef unsigned long long ull;

// ---------------- fp16 helpers ----------------
__device__ __forceinline__ uint32_t h2bits(__half2 h) {
    uint32_t u; *(__half2*)&u = h; return u;
}
__device__ __forceinline__ uint32_t packh2(float lo, float hi) {
    return h2bits(__floats2half2_rn(lo, hi));
}
__device__ __forceinline__ uint32_t smem_to_u32(const void* p) {
    uint32_t a; asm("{ .reg .u64 t; cvta.to.shared.u64 t, %1; cvt.u32.u64 %0, t; }" : "=r"(a) : "l"(p)); return a;
}

// ---------------- mma.sync + ldmatrix + cp.async (baseline PTX) ----------
__device__ __forceinline__ void mma_f16(float* c, const uint32_t* a, uint32_t b0, uint32_t b1) {
    asm volatile("mma.sync.aligned.m16n8k16.row.col.f32.f16.f16.f32 "
        "{%0,%1,%2,%3}, {%4,%5,%6,%7}, {%8,%9}, {%0,%1,%2,%3};"
        : "+f"(c[0]), "+f"(c[1]), "+f"(c[2]), "+f"(c[3])
        : "r"(a[0]), "r"(a[1]), "r"(a[2]), "r"(a[3]), "r"(b0), "r"(b1));
}
__device__ __forceinline__ void ldsm_x4(uint32_t* r, uint32_t addr) {
    asm volatile("ldmatrix.sync.aligned.m8n8.x4.shared.b16 {%0,%1,%2,%3}, [%4];"
        : "=r"(r[0]), "=r"(r[1]), "=r"(r[2]), "=r"(r[3]) : "r"(addr));
}
__device__ __forceinline__ void ldsm_x4_t(uint32_t* r, uint32_t addr) {
    asm volatile("ldmatrix.sync.aligned.m8n8.x4.trans.shared.b16 {%0,%1,%2,%3}, [%4];"
        : "=r"(r[0]), "=r"(r[1]), "=r"(r[2]), "=r"(r[3]) : "r"(addr));
}
__device__ __forceinline__ void cp_async16(uint32_t dst, const void* src) {
    asm volatile("cp.async.ca.shared.global [%0], [%1], 16;" :: "r"(dst), "l"(src) : "memory");
}
#define CP_COMMIT() asm volatile("cp.async.commit_group;" ::: "memory")
#define CP_WAIT0()  asm volatile("cp.async.wait_group 0;" ::: "memory")

// ---------------- scratch ----------------
__device__ float g_Q[NAC];                 // projected queries (fp32)
__device__ __half g_AOh[NAC], g_AOl[NAC];  // attn output hi/lo planes
__device__ __half g_INh[NAC], g_INl[NAC];  // inputs hi/lo planes
__device__ __half g_W[2][512 * 512];       // wq, wo single fp16 planes
__device__ ull g_maskBits[(size_t)BB * SS * SS / 64];   // 131072 units
__device__ int g_maskKind;
__device__ __half g_KVsp[2][NKV];          // fp16 planes: K, V

// ---------------- mask dtype detect ----------------
__global__ void detect_mask_kernel(const unsigned int* __restrict__ w)
{
    int i32ok = 1, f32ok = 1;
    for (int i = threadIdx.x; i < 16384; i += 256) {
        unsigned int v = w[i];
        if (v > 1u) i32ok = 0;
        if (v != 0u && v != 0x3F800000u) f32ok = 0;
    }
    i32ok = __syncthreads_and(i32ok);
    f32ok = __syncthreads_and(f32ok);
    if (threadIdx.x == 0) g_maskKind = i32ok ? 1 : (f32ok ? 2 : 0);
}

// ---------------- fused prep: bitpack + kv + w + in planes -----------------
__global__ __launch_bounds__(256)
void prep_kernel(const void* __restrict__ mask,
                 const float* __restrict__ K, const float* __restrict__ V,
                 const float* __restrict__ wq, const float* __restrict__ wo,
                 const float* __restrict__ A)
{
    const size_t tg = (size_t)blockIdx.x * 256 + threadIdx.x;   // 0..131071
    const int kind = g_maskKind;

    // ---- mask bitpack: unit = tg (full 131072 coverage) ----
    {
        ull bits = 0;
        if (kind == 1) {
            const int4* p = (const int4*)mask + tg * 16;
            #pragma unroll
            for (int w = 0; w < 16; ++w) {
                int4 a = p[w];
                bits |= ((ull)(a.x != 0)) << (4 * w) | ((ull)(a.y != 0)) << (4 * w + 1) |
                        ((ull)(a.z != 0)) << (4 * w + 2) | ((ull)(a.w != 0)) << (4 * w + 3);
            }
        } else if (kind == 2) {
            const float4* p = (const float4*)mask + tg * 16;
            #pragma unroll
            for (int w = 0; w < 16; ++w) {
                float4 a = p[w];
                bits |= ((ull)(a.x != 0.f)) << (4 * w) | ((ull)(a.y != 0.f)) << (4 * w + 1) |
                        ((ull)(a.z != 0.f)) << (4 * w + 2) | ((ull)(a.w != 0.f)) << (4 * w + 3);
            }
        } else {
            const ull* p = (const ull*)mask + tg * 8;
            #pragma unroll
            for (int w = 0; w < 8; ++w) {
                ull v = p[w];
                #pragma unroll
                for (int b8 = 0; b8 < 8; ++b8)
                    bits |= ((ull)(((v >> (8 * b8)) & 0xffull) != 0)) << (8 * w + b8);
            }
        }
        g_maskBits[tg] = bits;
    }

    // ---- K/V + input planes (4 units/thread) ----
    #pragma unroll
    for (int j = 0; j < 4; ++j) {
        size_t u = tg + (size_t)131072 * j;
        {
            float4 v = ((const float4*)K)[u];
            ((uint2*)g_KVsp[0])[u] = make_uint2(packh2(v.x, v.y), packh2(v.z, v.w));
        }
        {
            float4 v = ((const float4*)V)[u];
            ((uint2*)g_KVsp[1])[u] = make_uint2(packh2(v.x, v.y), packh2(v.z, v.w));
        }
        {
            float4 v = ((const float4*)A)[u];
            __half2 h01 = __floats2half2_rn(v.x, v.y);
            __half2 h23 = __floats2half2_rn(v.z, v.w);
            ((uint2*)g_INh)[u] = make_uint2(h2bits(h01), h2bits(h23));
            ((uint2*)g_INl)[u] = make_uint2(
                packh2(v.x - __low2float(h01), v.y - __high2float(h01)),
                packh2(v.z - __low2float(h23), v.w - __high2float(h23)));
        }
    }

    // ---- weight planes (65536 units) ----
    if (tg < 65536) {
        {
            float4 v = ((const float4*)wq)[tg];
            ((uint2*)g_W[0])[tg] = make_uint2(packh2(v.x, v.y), packh2(v.z, v.w));
        }
        {
            float4 v = ((const float4*)wo)[tg];
            ((uint2*)g_W[1])[tg] = make_uint2(packh2(v.x, v.y), packh2(v.z, v.w));
        }
    }
}

// ---------------- fp16 HMMA GEMM, BK=64, cp.async double-buffered ----------
#define GLA 72
#define GLB 72
#define GA_PL (128 * GLA)
#define GB_OFF (2 * GA_PL)
#define GBUF (GB_OFF + 64 * GLB)
#define GBUFB (GBUF * 2)

__global__ __launch_bounds__(128, 2)
void gemm_fp16_kernel(const __half* __restrict__ Ah, const __half* __restrict__ Al,
                      const __half* __restrict__ W, float* __restrict__ C)
{
    extern __shared__ __align__(16) __half gdyn[];

    const int tid = threadIdx.x;
    const int warp = tid >> 5, lane = tid & 31;
    const int g = lane >> 3, lrow = lane & 7;
    const int mbase = blockIdx.x * 128, nbase = blockIdx.y * 64;

    float Ca[2][8][4];
    #pragma unroll
    for (int i = 0; i < 2; ++i)
        #pragma unroll
        for (int j = 0; j < 8; ++j)
            #pragma unroll
            for (int r = 0; r < 4; ++r) Ca[i][j][r] = 0.f;

    const uint32_t uS = smem_to_u32(gdyn);
    const int arow = warp * 32 + (g & 1) * 8 + lrow;
    const int acol = (g >> 1) * 8;
    const uint32_t bOff = (uint32_t)(((g & 1) * 8 + lrow) * GLB + (g >> 1) * 8) * 2;

    auto stage = [&](int kk, int sel) {
        uint32_t dbase = uS + sel * GBUFB;
        #pragma unroll
        for (int j = 0; j < 16; ++j) {
            int idx = tid + 128 * j;
            int plane = idx >> 10, rem = idx & 1023;
            int row = rem >> 3, seg = rem & 7;
            const __half* src = (plane ? Al : Ah) + (size_t)(mbase + row) * 512 + kk + seg * 8;
            uint32_t dst = dbase + (uint32_t)(plane * GA_PL + row * GLA + seg * 8) * 2;
            cp_async16(dst, src);
        }
        #pragma unroll
        for (int j = 0; j < 4; ++j) {
            int idx = tid + 128 * j;
            int row = idx >> 3, seg = idx & 7;
            const __half* src = W + (size_t)(kk + row) * 512 + nbase + seg * 8;
            uint32_t dst = dbase + (uint32_t)(GB_OFF + row * GLB + seg * 8) * 2;
            cp_async16(dst, src);
        }
        CP_COMMIT();
    };

    stage(0, 0);

    #pragma unroll 1
    for (int c = 0; c < 8; ++c) {
        CP_WAIT0();
        __syncthreads();
        if (c + 1 < 8) stage((c + 1) * 64, (c + 1) & 1);

        const uint32_t ubase = uS + (c & 1) * GBUFB;
        uint32_t Af[2][2][4][4];
        #pragma unroll
        for (int p = 0; p < 2; ++p)
            #pragma unroll
            for (int i = 0; i < 2; ++i)
                #pragma unroll
                for (int kb = 0; kb < 4; ++kb)
                    ldsm_x4(Af[p][i][kb], ubase +
                        (uint32_t)(p * GA_PL + (arow + i * 16) * GLA + acol + kb * 16) * 2);

        #pragma unroll
        for (int np = 0; np < 4; ++np) {
            #pragma unroll
            for (int kb = 0; kb < 4; ++kb) {
                uint32_t Bk[4];
                uint32_t off = (uint32_t)(GB_OFF * 2) + (uint32_t)(kb * 16 * GLB + np * 16) * 2;
                ldsm_x4_t(Bk, ubase + off + bOff);
                #pragma unroll
                for (int i = 0; i < 2; ++i) mma_f16(Ca[i][2 * np], Af[0][i][kb], Bk[0], Bk[1]);
                #pragma unroll
                for (int i = 0; i < 2; ++i) mma_f16(Ca[i][2 * np + 1], Af[0][i][kb], Bk[2], Bk[3]);
                #pragma unroll
                for (int i = 0; i < 2; ++i) mma_f16(Ca[i][2 * np], Af[1][i][kb], Bk[0], Bk[1]);
                #pragma unroll
                for (int i = 0; i < 2; ++i) mma_f16(Ca[i][2 * np + 1], Af[1][i][kb], Bk[2], Bk[3]);
            }
        }
    }

    #pragma unroll
    for (int i = 0; i < 2; ++i) {
        int r0 = mbase + warp * 32 + i * 16 + (lane >> 2);
        float* c0 = C + (size_t)r0 * 512 + nbase;
        float* c1 = c0 + (size_t)8 * 512;
        #pragma unroll
        for (int nb = 0; nb < 8; ++nb) {
            int d = nb * 8 + (lane & 3) * 2;
            *(float2*)(c0 + d) = make_float2(Ca[i][nb][0], Ca[i][nb][1]);
            *(float2*)(c1 + d) = make_float2(Ca[i][nb][2], Ca[i][nb][3]);
        }
    }
}

// ---------------- HMMA flash attention, occ-3, per-i S pass ----------------
#define LST 72
#define TS (64 * LST)
#define PLB (TS * 2)
#define BUFB (2 * PLB)

__global__ __launch_bounds__(128, 3)
void attn_mma_kernel(const ull* __restrict__ mbits, const float* __restrict__ Q)
{
    extern __shared__ __align__(16) __half dyn[];

    const int b = blockIdx.z, h = blockIdx.y;
    const int qbase = blockIdx.x * 128;
    const int tid = threadIdx.x;
    const int warp = tid >> 5, lane = tid & 31;
    const int g = lane >> 3, lrow = lane & 7;

    {
        const float4* qr = (const float4*)(Q + (size_t)(b * SS + qbase + tid) * EE + h * DD);
        uint32_t* dh = (uint32_t*)(dyn + (tid >= 64 ? TS : 0) + (tid & 63) * LST);
        #pragma unroll
        for (int i = 0; i < 16; ++i) {
            float4 v = qr[i];
            dh[2 * i] = packh2(v.x * 0.125f, v.y * 0.125f);
            dh[2 * i + 1] = packh2(v.z * 0.125f, v.w * 0.125f);
        }
    }
    __syncthreads();

    uint32_t Qh[2][4][4];
    {
        const __half* bh = (warp < 2) ? dyn : dyn + TS;
        const int rowbase = (warp & 1) * 32;
        const int arow = rowbase + (g & 1) * 8 + lrow;
        const int acol = (g >> 1) * 8;
        #pragma unroll
        for (int i = 0; i < 2; ++i)
            #pragma unroll
            for (int kb = 0; kb < 4; ++kb)
                ldsm_x4(Qh[i][kb], smem_to_u32(bh + (arow + i * 16) * LST + acol + kb * 16));
    }
    __syncthreads();

    float Oa[2][8][4];
    #pragma unroll
    for (int i = 0; i < 2; ++i)
        #pragma unroll
        for (int j = 0; j < 8; ++j)
            #pragma unroll
            for (int r = 0; r < 4; ++r) Oa[i][j][r] = 0.f;
    float lsum[4] = {0.f, 0.f, 0.f, 0.f};

    const uint32_t uB = smem_to_u32(dyn);
    const uint32_t kOff = (uint32_t)(((g >> 1) * 8 + lrow) * LST + (g & 1) * 8) * 2;
    const uint32_t vOff = (uint32_t)(((g & 1) * 8 + lrow) * LST + (g >> 1) * 8) * 2;
    const ull* mrow = mbits + (size_t)(b * SS + qbase + warp * 32) * (SS / 64);

    auto stage = [&](int kt, int sel) {
        uint32_t dbase = uB + sel * BUFB;
        #pragma unroll
        for (int j = 0; j < 8; ++j) {
            int idx = tid + 128 * j;
            int plane = idx >> 9;
            int rem = idx & 511;
            int row = rem >> 3, seg = rem & 7;
            const __half* src = g_KVsp[plane] +
                ((size_t)(b * SS + kt + row) * HH + h) * DD + seg * 8;
            uint32_t dst = dbase + (uint32_t)(plane * TS + row * LST + seg * 8) * 2;
            cp_async16(dst, src);
        }
        CP_COMMIT();
    };

    stage(0, 0);

    #pragma unroll 1
    for (int t = 0; t < SS / 64; ++t) {
        CP_WAIT0();
        __syncthreads();
        if (t + 1 < SS / 64) stage((t + 1) * 64, (t + 1) & 1);

        const uint32_t ubase = uB + (t & 1) * BUFB;
        const uint32_t uK = ubase, uV = ubase + PLB;

        // hoisted mask words (overlap LDG with MMA below)
        ull mw[2][2];
        #pragma unroll
        for (int i = 0; i < 2; ++i) {
            mw[i][0] = mrow[(size_t)(i * 16 + (lane >> 2)) * (SS / 64) + t];
            mw[i][1] = mrow[(size_t)(i * 16 + 8 + (lane >> 2)) * (SS / 64) + t];
        }

        uint32_t Ph[2][4][4];
        // ---- per-i: S pass + softmax (halves live S registers) ----
        #pragma unroll
        for (int i = 0; i < 2; ++i) {
            float S[8][4];
            #pragma unroll
            for (int j = 0; j < 8; ++j)
                #pragma unroll
                for (int r = 0; r < 4; ++r) S[j][r] = 0.f;

            #pragma unroll
            for (int np = 0; np < 4; ++np) {
                #pragma unroll
                for (int kb = 0; kb < 4; ++kb) {
                    uint32_t Bk[4];
                    uint32_t off = (uint32_t)(np * 16 * LST + kb * 16) * 2;
                    ldsm_x4(Bk, uK + off + kOff);
                    mma_f16(S[2 * np], Qh[i][kb], Bk[0], Bk[1]);
                    mma_f16(S[2 * np + 1], Qh[i][kb], Bk[2], Bk[3]);
                }
            }

            ull mw0 = mw[i][0], mw1 = mw[i][1];
            #pragma unroll
            for (int nb = 0; nb < 8; ++nb) {
                int p0 = nb * 8 + (lane & 3) * 2;
                float e0 = ((mw0 >> p0) & 1ull) ? 0.f : __expf(S[nb][0]);
                float e1 = ((mw0 >> (p0 + 1)) & 1ull) ? 0.f : __expf(S[nb][1]);
                float e2 = ((mw1 >> p0) & 1ull) ? 0.f : __expf(S[nb][2]);
                float e3 = ((mw1 >> (p0 + 1)) & 1ull) ? 0.f : __expf(S[nb][3]);
                lsum[i * 2] += e0 + e1;
                lsum[i * 2 + 1] += e2 + e3;
                int kb = nb >> 1, sub = (nb & 1) * 2;
                Ph[i][kb][sub] = packh2(e0, e1);
                Ph[i][kb][sub + 1] = packh2(e2, e3);
            }
        }

        // ---- joint PV ----
        #pragma unroll
        for (int dp = 0; dp < 4; ++dp) {
            #pragma unroll
            for (int kb = 0; kb < 4; ++kb) {
                uint32_t Bv[4];
                uint32_t off = (uint32_t)(kb * 16 * LST + dp * 16) * 2;
                ldsm_x4_t(Bv, uV + off + vOff);
                #pragma unroll
                for (int i = 0; i < 2; ++i) mma_f16(Oa[i][2 * dp], Ph[i][kb], Bv[0], Bv[1]);
                #pragma unroll
                for (int i = 0; i < 2; ++i) mma_f16(Oa[i][2 * dp + 1], Ph[i][kb], Bv[2], Bv[3]);
            }
        }
    }

    #pragma unroll
    for (int i = 0; i < 4; ++i) {
        lsum[i] += __shfl_xor_sync(0xffffffffu, lsum[i], 1);
        lsum[i] += __shfl_xor_sync(0xffffffffu, lsum[i], 2);
    }
    #pragma unroll
    for (int i = 0; i < 2; ++i) {
        float inv0 = 1.f / lsum[i * 2];
        float inv1 = 1.f / lsum[i * 2 + 1];
        int r0 = qbase + warp * 32 + i * 16 + (lane >> 2);
        size_t base0 = (size_t)(b * SS + r0) * EE + h * DD;
        size_t base1 = base0 + (size_t)8 * EE;
        #pragma unroll
        for (int nb = 0; nb < 8; ++nb) {
            int d = nb * 8 + (lane & 3) * 2;
            float v0 = Oa[i][nb][0] * inv0, v1 = Oa[i][nb][1] * inv0;
            float v2 = Oa[i][nb][2] * inv1, v3 = Oa[i][nb][3] * inv1;
            __half2 h01 = __floats2half2_rn(v0, v1);
            __half2 h23 = __floats2half2_rn(v2, v3);
            *(uint32_t*)(g_AOh + base0 + d) = h2bits(h01);
            *(uint32_t*)(g_AOl + base0 + d) =
                packh2(v0 - __low2float(h01), v1 - __high2float(h01));
            *(uint32_t*)(g_AOh + base1 + d) = h2bits(h23);
            *(uint32_t*)(g_AOl + base1 + d) =
                packh2(v2 - __low2float(h23), v3 - __high2float(h23));
        }
    }
}

// ---------------- launch ----------------
extern "C" void kernel_launch(void* const* d_in, const int* in_sizes, int n_in,
                              void* d_out, int out_size)
{
    const float* inputs = (const float*)d_in[0];
    const float* keys = (const float*)d_in[1];
    const float* values = (const float*)d_in[2];
    const float* wq = (const float*)d_in[3];
    const float* wo = (const float*)d_in[4];
    const void* mask_raw = d_in[5];
    float* out = (float*)d_out;

    float* qbuf; ull* mbits;
    __half *inh, *inl, *aoh, *aol, *w0, *w1;
    cudaGetSymbolAddress((void**)&qbuf, g_Q);
    cudaGetSymbolAddress((void**)&mbits, g_maskBits);
    cudaGetSymbolAddress((void**)&inh, g_INh);
    cudaGetSymbolAddress((void**)&inl, g_INl);
    cudaGetSymbolAddress((void**)&aoh, g_AOh);
    cudaGetSymbolAddress((void**)&aol, g_AOl);
    cudaGetSymbolAddress((void**)&w0, g_W);
    w1 = w0 + 512 * 512;

    static int attr_set = 0;
    if (!attr_set) {
        cudaFuncSetAttribute(attn_mma_kernel,
                             cudaFuncAttributeMaxDynamicSharedMemorySize, 2 * BUFB);
        cudaFuncSetAttribute(gemm_fp16_kernel,
                             cudaFuncAttributeMaxDynamicSharedMemorySize, 2 * GBUFB);
        attr_set = 1;
    }

    detect_mask_kernel<<<1, 256>>>((const unsigned int*)mask_raw);
    prep_kernel<<<512, 256>>>(mask_raw, keys, values, wq, wo, inputs);

    dim3 ggrid(32, 8);
    gemm_fp16_kernel<<<ggrid, 128, 2 * GBUFB>>>(inh, inl, w0, qbuf);
    attn_mma_kernel<<<dim3(SS / 128, HH, BB), 128, 2 * BUFB>>>(mbits, qbuf);
    gemm_fp16_kernel<<<ggrid, 128, 2 * GBUFB>>>(aoh, aol, w1, out);
}